// round 9
// baseline (speedup 1.0000x reference)
#include <cuda_runtime.h>
#include <cstdint>
#include <cstddef>

// Problem constants
#define Bb   8
#define Ll   1024
#define Dd   512
#define Hh   8
#define Qd   64
#define Mrows (Bb*Ll)          // 8192

// ---------------------------------------------------------------------------
// Scratch (no cudaMalloc allowed): 5 x 16MB fp32 buffers
// ---------------------------------------------------------------------------
__device__ float g_xr[Mrows*Dd];
__device__ float g_Q [Mrows*Dd];
__device__ float g_Kt[Mrows*Dd];   // K stored transposed: Kt[(b*512 + h*64 + d)*1024 + l]
__device__ float g_V [Mrows*Dd];
__device__ float g_mg[Mrows*Dd];   // merged[b,l, d*H + h]

// ---------------------------------------------------------------------------
// GEMM: C[M,N] = A[M,K] @ W[N,K]^T + bias.  M=8192, N=K=512 (fixed).
// transK=1: write result transposed into Kt layout [(b*512+n)*1024 + (m%1024)]
// 128x128 tile, BK=16, 256 threads, 8x8 micro-tile.
// ---------------------------------------------------------------------------
__global__ __launch_bounds__(256, 2)
void gemm_bias_k(const float* __restrict__ A, const float* __restrict__ W,
                 const float* __restrict__ bias, float* __restrict__ C,
                 int transK)
{
    const int Kd = 512;
    __shared__ float As[16][132];   // [k][m], padded
    __shared__ float Ws[16][132];   // [k][n], padded

    const int bm  = blockIdx.x * 128;
    const int bn  = blockIdx.y * 128;
    const int tid = threadIdx.x;
    const int tx  = tid & 15;       // N micro index
    const int ty  = tid >> 4;       // M micro index

    float acc[8][8];
#pragma unroll
    for (int i = 0; i < 8; i++)
#pragma unroll
        for (int j = 0; j < 8; j++) acc[i][j] = 0.0f;

    for (int k0 = 0; k0 < Kd; k0 += 16) {
#pragma unroll
        for (int i = 0; i < 2; i++) {
            int idx = tid + i * 256;          // 0..511
            int row = idx >> 2;               // 0..127
            int kc  = (idx & 3) << 2;         // 0,4,8,12
            float4 va = *reinterpret_cast<const float4*>(&A[(size_t)(bm + row) * Kd + k0 + kc]);
            As[kc + 0][row] = va.x; As[kc + 1][row] = va.y;
            As[kc + 2][row] = va.z; As[kc + 3][row] = va.w;
            float4 vw = *reinterpret_cast<const float4*>(&W[(size_t)(bn + row) * Kd + k0 + kc]);
            Ws[kc + 0][row] = vw.x; Ws[kc + 1][row] = vw.y;
            Ws[kc + 2][row] = vw.z; Ws[kc + 3][row] = vw.w;
        }
        __syncthreads();

#pragma unroll
        for (int k = 0; k < 16; k++) {
            float a[8], b[8];
            *reinterpret_cast<float4*>(&a[0]) = *reinterpret_cast<const float4*>(&As[k][ty * 8]);
            *reinterpret_cast<float4*>(&a[4]) = *reinterpret_cast<const float4*>(&As[k][ty * 8 + 4]);
            *reinterpret_cast<float4*>(&b[0]) = *reinterpret_cast<const float4*>(&Ws[k][tx * 8]);
            *reinterpret_cast<float4*>(&b[4]) = *reinterpret_cast<const float4*>(&Ws[k][tx * 8 + 4]);
#pragma unroll
            for (int i = 0; i < 8; i++)
#pragma unroll
                for (int j = 0; j < 8; j++)
                    acc[i][j] = fmaf(a[i], b[j], acc[i][j]);
        }
        __syncthreads();
    }

    if (!transK) {
#pragma unroll
        for (int i = 0; i < 8; i++) {
            int m = bm + ty * 8 + i;
            int n0 = bn + tx * 8;
            float4 o0, o1;
            o0.x = acc[i][0] + bias[n0 + 0];
            o0.y = acc[i][1] + bias[n0 + 1];
            o0.z = acc[i][2] + bias[n0 + 2];
            o0.w = acc[i][3] + bias[n0 + 3];
            o1.x = acc[i][4] + bias[n0 + 4];
            o1.y = acc[i][5] + bias[n0 + 5];
            o1.z = acc[i][6] + bias[n0 + 6];
            o1.w = acc[i][7] + bias[n0 + 7];
            *reinterpret_cast<float4*>(&C[(size_t)m * 512 + n0])     = o0;
            *reinterpret_cast<float4*>(&C[(size_t)m * 512 + n0 + 4]) = o1;
        }
    } else {
        // Kt[(b*512 + n)*1024 + l], where m = b*1024 + l
#pragma unroll
        for (int i = 0; i < 8; i++) {
            int m = bm + ty * 8 + i;
            int bidx = m >> 10;
            int l    = m & 1023;
#pragma unroll
            for (int j = 0; j < 8; j++) {
                int n = bn + tx * 8 + j;
                C[((size_t)(bidx * 512 + n)) * 1024 + l] = acc[i][j] + bias[n];
            }
        }
    }
}

// ---------------------------------------------------------------------------
// Fused attention: per block = (b, h, 32 Q rows).
// Full 32x1024 logit tile lives in smem -> scores written to gmem exactly once.
// S phase:  32x256-col tiles, 4x8 micro-tiles, K loaded from pre-transposed Kt.
// V phase:  2x4 micro-tiles, O = P@V; write to merged[b,l, d*H+h].
// ---------------------------------------------------------------------------
#define SROW 1032                                // padded row stride of S
#define ATTN_SMEM_FLOATS (32*SROW + 64*36 + 256*68)
#define ATTN_SMEM_BYTES  (ATTN_SMEM_FLOATS * 4)  // 210,944 B

__global__ __launch_bounds__(256)
void attn_k(const float* __restrict__ Q, const float* __restrict__ Kt,
            const float* __restrict__ V, float* __restrict__ scores,
            float* __restrict__ merged)
{
    extern __shared__ float sm[];
    float* S   = sm;                    // [32][SROW]
    float* Qst = S + 32 * SROW;         // [64][36]  : Qst[d][r] (pre-scaled by 1/8)
    float* KV  = Qst + 64 * 36;         // K phase: [64][260]=Kst[d][c]; V phase: [256][68]=Vs[j][d]

    const int tid = threadIdx.x;
    const int qt  = blockIdx.x;         // 0..31
    const int h   = blockIdx.y;         // 0..7
    const int b   = blockIdx.z;         // 0..7
    const int l0  = qt * 32;

    // ---- load Q tile (scaled by 1/sqrt(Qd) = 0.125), transposed into smem ----
    {
        const float* Qg = Q + ((size_t)(b * 1024 + l0)) * 512 + h * 64;
#pragma unroll
        for (int i = 0; i < 2; i++) {
            int idx = tid + i * 256;          // 0..511
            int r   = idx >> 4;               // 0..31
            int d4  = (idx & 15) << 2;        // 0..60
            float4 v = *reinterpret_cast<const float4*>(&Qg[(size_t)r * 512 + d4]);
            Qst[(d4 + 0) * 36 + r] = v.x * 0.125f;
            Qst[(d4 + 1) * 36 + r] = v.y * 0.125f;
            Qst[(d4 + 2) * 36 + r] = v.z * 0.125f;
            Qst[(d4 + 3) * 36 + r] = v.w * 0.125f;
        }
    }

    const int lane = tid & 31;
    const int w    = tid >> 5;          // warp id 0..7

    // ---- S phase: logits tile [32 x 1024] into smem ----
    {
        const int c0 = lane * 8;        // 8 cols per lane (0..248)
        const int r0 = w * 4;           // 4 rows per warp (0..28)
        for (int jt = 0; jt < 4; jt++) {
            __syncthreads();            // Qst ready (jt=0) / KV free (jt>0)
            const float* Kg = Kt + ((size_t)(b * 512 + h * 64)) * 1024 + jt * 256;
#pragma unroll
            for (int i = 0; i < 16; i++) {
                int idx = tid + i * 256;       // 0..4095
                int d   = idx >> 6;            // 0..63
                int c4  = (idx & 63) << 2;     // 0..252
                float4 v = *reinterpret_cast<const float4*>(&Kg[(size_t)d * 1024 + c4]);
                *reinterpret_cast<float4*>(&KV[d * 260 + c4]) = v;
            }
            __syncthreads();

            float acc[4][8];
#pragma unroll
            for (int i = 0; i < 4; i++)
#pragma unroll
                for (int j = 0; j < 8; j++) acc[i][j] = 0.0f;

#pragma unroll 8
            for (int d = 0; d < 64; d++) {
                float4 aq = *reinterpret_cast<const float4*>(&Qst[d * 36 + r0]);
                float4 b0 = *reinterpret_cast<const float4*>(&KV[d * 260 + c0]);
                float4 b1 = *reinterpret_cast<const float4*>(&KV[d * 260 + c0 + 4]);
                float av[4] = {aq.x, aq.y, aq.z, aq.w};
                float bv[8] = {b0.x, b0.y, b0.z, b0.w, b1.x, b1.y, b1.z, b1.w};
#pragma unroll
                for (int i = 0; i < 4; i++)
#pragma unroll
                    for (int j = 0; j < 8; j++)
                        acc[i][j] = fmaf(av[i], bv[j], acc[i][j]);
            }

#pragma unroll
            for (int i = 0; i < 4; i++) {
                float* srow = &S[(size_t)(r0 + i) * SROW + jt * 256 + c0];
                *reinterpret_cast<float4*>(srow)     = make_float4(acc[i][0], acc[i][1], acc[i][2], acc[i][3]);
                *reinterpret_cast<float4*>(srow + 4) = make_float4(acc[i][4], acc[i][5], acc[i][6], acc[i][7]);
            }
        }
        __syncthreads();
    }

    // ---- softmax per row (warp w owns rows 4w..4w+3); write scores once ----
    {
        for (int rr = 0; rr < 4; rr++) {
            int r = w * 4 + rr;
            float* row = &S[(size_t)r * SROW];
            float mx = -1e30f;
            for (int j = lane; j < 1024; j += 32) mx = fmaxf(mx, row[j]);
#pragma unroll
            for (int o = 16; o; o >>= 1) mx = fmaxf(mx, __shfl_xor_sync(0xffffffffu, mx, o));
            float s = 0.0f;
            for (int j = lane; j < 1024; j += 32) {
                float e = __expf(row[j] - mx);
                row[j] = e;
                s += e;
            }
#pragma unroll
            for (int o = 16; o; o >>= 1) s += __shfl_xor_sync(0xffffffffu, s, o);
            float inv = 1.0f / s;
            float* sg = scores + (((size_t)(b * 8 + h)) * 1024 + (l0 + r)) * 1024;
            for (int j = lane; j < 1024; j += 32) {
                float p = row[j] * inv;
                row[j] = p;
                sg[j]  = p;
            }
        }
    }

    // ---- V phase: O = P @ V ----
    {
        const int tx  = tid & 15;
        const int tyv = tid >> 4;
        const int d0  = tx * 4;         // 4 head-dims per lane
        const int r0  = tyv * 2;        // 2 rows per thread
        float o[2][4];
#pragma unroll
        for (int i = 0; i < 2; i++)
#pragma unroll
            for (int j = 0; j < 4; j++) o[i][j] = 0.0f;

        for (int jt = 0; jt < 4; jt++) {
            __syncthreads();            // softmax S visible (jt=0) / KV free
            const float* Vg = V + ((size_t)(b * 1024 + jt * 256)) * 512 + h * 64;
#pragma unroll
            for (int i = 0; i < 16; i++) {
                int idx = tid + i * 256;      // 0..4095
                int jr  = idx >> 4;           // 0..255
                int d4  = (idx & 15) << 2;    // 0..60
                float4 v = *reinterpret_cast<const float4*>(&Vg[(size_t)jr * 512 + d4]);
                *reinterpret_cast<float4*>(&KV[jr * 68 + d4]) = v;
            }
            __syncthreads();

#pragma unroll 8
            for (int jj = 0; jj < 256; jj++) {
                float4 bv = *reinterpret_cast<const float4*>(&KV[jj * 68 + d0]);
                float a0 = S[(size_t)(r0 + 0) * SROW + jt * 256 + jj];
                float a1 = S[(size_t)(r0 + 1) * SROW + jt * 256 + jj];
                o[0][0] = fmaf(a0, bv.x, o[0][0]);
                o[0][1] = fmaf(a0, bv.y, o[0][1]);
                o[0][2] = fmaf(a0, bv.z, o[0][2]);
                o[0][3] = fmaf(a0, bv.w, o[0][3]);
                o[1][0] = fmaf(a1, bv.x, o[1][0]);
                o[1][1] = fmaf(a1, bv.y, o[1][1]);
                o[1][2] = fmaf(a1, bv.z, o[1][2]);
                o[1][3] = fmaf(a1, bv.w, o[1][3]);
            }
        }

        // merged[b, l, d*H + h]
        float* mg = merged + ((size_t)(b * 1024 + l0)) * 512 + h;
#pragma unroll
        for (int i = 0; i < 2; i++)
#pragma unroll
            for (int jd = 0; jd < 4; jd++)
                mg[(size_t)(r0 + i) * 512 + (size_t)(d0 + jd) * 8] = o[i][jd];
    }
}

// ---------------------------------------------------------------------------
// Launch
// ---------------------------------------------------------------------------
extern "C" void kernel_launch(void* const* d_in, const int* in_sizes, int n_in,
                              void* d_out, int out_size)
{
    const float* x  = (const float*)d_in[0];
    const float* Wc = (const float*)d_in[1];
    const float* bc = (const float*)d_in[2];
    const float* Wq = (const float*)d_in[3];
    const float* bq = (const float*)d_in[4];
    const float* Wk = (const float*)d_in[5];
    const float* bk = (const float*)d_in[6];
    const float* Wv = (const float*)d_in[7];
    const float* bv = (const float*)d_in[8];
    const float* Wo = (const float*)d_in[9];
    const float* bo = (const float*)d_in[10];

    float* out    = (float*)d_out;                            // [B, L, D]
    float* scores = out + (size_t)Bb * Ll * Dd;               // [B, H, L, L]

    float *xr, *Qb, *Ktb, *Vb, *mg;
    cudaGetSymbolAddress((void**)&xr,  g_xr);
    cudaGetSymbolAddress((void**)&Qb,  g_Q);
    cudaGetSymbolAddress((void**)&Ktb, g_Kt);
    cudaGetSymbolAddress((void**)&Vb,  g_V);
    cudaGetSymbolAddress((void**)&mg,  g_mg);

    cudaFuncSetAttribute((const void*)attn_k,
                         cudaFuncAttributeMaxDynamicSharedMemorySize,
                         ATTN_SMEM_BYTES);

    dim3 gg(Mrows / 128, Dd / 128);   // (64, 4)

    gemm_bias_k<<<gg, 256>>>(x,  Wc, bc, xr,  0);   // x_r = x @ Wc^T + bc
    gemm_bias_k<<<gg, 256>>>(x,  Wq, bq, Qb,  0);   // Q
    gemm_bias_k<<<gg, 256>>>(xr, Wk, bk, Ktb, 1);   // K, written transposed
    gemm_bias_k<<<gg, 256>>>(xr, Wv, bv, Vb,  0);   // V
    attn_k<<<dim3(32, Hh, Bb), 256, ATTN_SMEM_BYTES>>>(Qb, Ktb, Vb, scores, mg);
    gemm_bias_k<<<gg, 256>>>(mg, Wo, bo, out, 0);   // out = merged @ Wo^T + bo
}

// round 12
// speedup vs baseline: 1.1823x; 1.1823x over previous
#include <cuda_runtime.h>
#include <cuda_bf16.h>
#include <cstdint>
#include <cstddef>

// Problem constants
#define Bb   8
#define Ll   1024
#define Dd   512
#define Hh   8
#define Qd   64
#define Mrows (Bb*Ll)          // 8192

// ---------------------------------------------------------------------------
// Scratch (no cudaMalloc allowed)
// ---------------------------------------------------------------------------
__device__ float g_Q [Mrows*Dd];
__device__ float g_Kt[Mrows*Dd];   // Kt[(b*512 + h*64 + d)*1024 + l]
__device__ float g_V [Mrows*Dd];
__device__ float g_mg[Mrows*Dd];   // merged[b,l, d*H + h]

__device__ __nv_bfloat16 g_xhi [Mrows*Dd];
__device__ __nv_bfloat16 g_xlo [Mrows*Dd];
__device__ __nv_bfloat16 g_xrhi[Mrows*Dd];
__device__ __nv_bfloat16 g_xrlo[Mrows*Dd];
__device__ __nv_bfloat16 g_mghi[Mrows*Dd];
__device__ __nv_bfloat16 g_mglo[Mrows*Dd];
__device__ __nv_bfloat16 g_whi [5*Dd*Dd];   // Wc,Wq,Wk,Wv,Wo
__device__ __nv_bfloat16 g_wlo [5*Dd*Dd];

// ---------------------------------------------------------------------------
// Warp MMA helpers (HMMA — available on plain sm_103)
// ---------------------------------------------------------------------------
__device__ __forceinline__ uint32_t smem_u32(const void* p) {
    uint32_t a;
    asm("{ .reg .u64 t; cvta.to.shared.u64 t, %1; cvt.u32.u64 %0, t; }" : "=r"(a) : "l"(p));
    return a;
}
__device__ __forceinline__ void ldsm_x4(uint32_t* r, uint32_t addr) {
    asm volatile("ldmatrix.sync.aligned.m8n8.x4.shared.b16 {%0,%1,%2,%3}, [%4];"
        : "=r"(r[0]), "=r"(r[1]), "=r"(r[2]), "=r"(r[3]) : "r"(addr));
}
__device__ __forceinline__ void mma16816(float* c, const uint32_t* a, const uint32_t* b) {
    asm volatile("mma.sync.aligned.m16n8k16.row.col.f32.bf16.bf16.f32 "
        "{%0,%1,%2,%3}, {%4,%5,%6,%7}, {%8,%9}, {%0,%1,%2,%3};"
        : "+f"(c[0]), "+f"(c[1]), "+f"(c[2]), "+f"(c[3])
        : "r"(a[0]), "r"(a[1]), "r"(a[2]), "r"(a[3]), "r"(b[0]), "r"(b[1]));
}

// ---------------------------------------------------------------------------
// fp32 -> bf16 hi/lo split
// ---------------------------------------------------------------------------
__global__ void cvt_split(const float* __restrict__ in,
                          __nv_bfloat16* __restrict__ hi,
                          __nv_bfloat16* __restrict__ lo, int n4)
{
    int i = blockIdx.x * blockDim.x + threadIdx.x;
    if (i >= n4) return;
    float4 v = reinterpret_cast<const float4*>(in)[i];
    __nv_bfloat16 h0 = __float2bfloat16(v.x);
    __nv_bfloat16 h1 = __float2bfloat16(v.y);
    __nv_bfloat16 h2 = __float2bfloat16(v.z);
    __nv_bfloat16 h3 = __float2bfloat16(v.w);
    __nv_bfloat162 ph0; ph0.x = h0; ph0.y = h1;
    __nv_bfloat162 ph1; ph1.x = h2; ph1.y = h3;
    __nv_bfloat162 pl0;
    pl0.x = __float2bfloat16(v.x - __bfloat162float(h0));
    pl0.y = __float2bfloat16(v.y - __bfloat162float(h1));
    __nv_bfloat162 pl1;
    pl1.x = __float2bfloat16(v.z - __bfloat162float(h2));
    pl1.y = __float2bfloat16(v.w - __bfloat162float(h3));
    reinterpret_cast<__nv_bfloat162*>(hi)[i*2]   = ph0;
    reinterpret_cast<__nv_bfloat162*>(hi)[i*2+1] = ph1;
    reinterpret_cast<__nv_bfloat162*>(lo)[i*2]   = pl0;
    reinterpret_cast<__nv_bfloat162*>(lo)[i*2+1] = pl1;
}

// ---------------------------------------------------------------------------
// HMMA split-precision GEMM: C[M,N] = (Ahi+Alo)[M,512] @ (Whi+Wlo)[N,512]^T + bias
// Tile 128x128, BK=32, 8 warps (2x4), warp tile 64x32, mma.m16n8k16.bf16.
// mode 0: C fp32 row-major.  mode 1: C transposed Kt layout.  mode 2: bf16 hi/lo.
// ---------------------------------------------------------------------------
#define LDT 40   // padded smem row stride (bf16 elems); 80B -> conflict-free LDSM

__global__ __launch_bounds__(256, 1)
void tg_gemm(const __nv_bfloat16* __restrict__ Ahi, const __nv_bfloat16* __restrict__ Alo,
             const __nv_bfloat16* __restrict__ Whi, const __nv_bfloat16* __restrict__ Wlo,
             const float* __restrict__ bias, float* __restrict__ C,
             __nv_bfloat16* __restrict__ Chi, __nv_bfloat16* __restrict__ Clo,
             int mode)
{
    __shared__ __nv_bfloat16 sAhi[128*LDT];
    __shared__ __nv_bfloat16 sAlo[128*LDT];
    __shared__ __nv_bfloat16 sWhi[128*LDT];
    __shared__ __nv_bfloat16 sWlo[128*LDT];

    const int tid  = threadIdx.x;
    const int wid  = tid >> 5;
    const int lane = tid & 31;
    const int bm   = blockIdx.x * 128;
    const int bn   = blockIdx.y * 128;

    const int wm = (wid >> 2) * 64;   // 0 or 64
    const int wn = (wid & 3) * 32;    // 0,32,64,96

    float acc[4][4][4];
#pragma unroll
    for (int i = 0; i < 4; i++)
#pragma unroll
        for (int j = 0; j < 4; j++)
#pragma unroll
            for (int k = 0; k < 4; k++) acc[i][j][k] = 0.0f;

    // ldmatrix source addresses (byte addresses in shared space)
    const uint32_t uAhi = smem_u32(sAhi);
    const uint32_t uAlo = smem_u32(sAlo);
    const uint32_t uWhi = smem_u32(sWhi);
    const uint32_t uWlo = smem_u32(sWlo);
    // A: row = wm + mf*16 + lane%16 ; col = kstep*16 + (lane>>4)*8
    const int a_row = wm + (lane & 15);
    const int a_colb = ((lane >> 4) * 8) * 2;
    // B: row = wn + p*16 + (lane>>4)*8 + lane%8 ; col = kstep*16 + ((lane>>3)&1)*8
    const int b_row = wn + ((lane >> 4) << 3) + (lane & 7);
    const int b_colb = (((lane >> 3) & 1) * 8) * 2;

    // gmem load indexing: 512 uint4 per tile, 2 per thread
    const int l_row0 = tid >> 1;            // 0..127
    const int l_c0   = (tid & 1) * 2;       // uint4 index 0 or 2 (we do c and c+1)

    for (int c = 0; c < 16; c++) {
        const int k0 = c * 32;
        // ---- load 4 tiles [128 x 32 bf16] ----
#pragma unroll
        for (int cc = 0; cc < 2; cc++) {
            int c16 = l_c0 + cc;                 // 0..3 (8 bf16 each)
            size_t ga = (size_t)(bm + l_row0) * 512 + k0 + c16 * 8;
            size_t gw = (size_t)(bn + l_row0) * 512 + k0 + c16 * 8;
            int so = l_row0 * LDT + c16 * 8;
            *reinterpret_cast<uint4*>(&sAhi[so]) = *reinterpret_cast<const uint4*>(Ahi + ga);
            *reinterpret_cast<uint4*>(&sAlo[so]) = *reinterpret_cast<const uint4*>(Alo + ga);
            *reinterpret_cast<uint4*>(&sWhi[so]) = *reinterpret_cast<const uint4*>(Whi + gw);
            *reinterpret_cast<uint4*>(&sWlo[so]) = *reinterpret_cast<const uint4*>(Wlo + gw);
        }
        __syncthreads();

#pragma unroll
        for (int ks = 0; ks < 2; ks++) {
            const int kb = ks * 16 * 2;      // byte offset of k-step
            uint32_t af[4][4];
            uint32_t bh[2][4], bl[2][4];
            // A_hi fragments
#pragma unroll
            for (int mf = 0; mf < 4; mf++)
                ldsm_x4(af[mf], uAhi + (uint32_t)((a_row + mf * 16) * LDT * 2) + kb + a_colb);
            // B_hi / B_lo fragments (p covers n16 each)
#pragma unroll
            for (int p = 0; p < 2; p++) {
                uint32_t off = (uint32_t)((b_row + p * 16) * LDT * 2) + kb + b_colb;
                ldsm_x4(bh[p], uWhi + off);
                ldsm_x4(bl[p], uWlo + off);
            }
            // pass hi*hi and hi*lo
#pragma unroll
            for (int mf = 0; mf < 4; mf++)
#pragma unroll
                for (int nf = 0; nf < 4; nf++) {
                    mma16816(acc[mf][nf], af[mf], &bh[nf >> 1][(nf & 1) * 2]);
                    mma16816(acc[mf][nf], af[mf], &bl[nf >> 1][(nf & 1) * 2]);
                }
            // A_lo fragments (overwrite)
#pragma unroll
            for (int mf = 0; mf < 4; mf++)
                ldsm_x4(af[mf], uAlo + (uint32_t)((a_row + mf * 16) * LDT * 2) + kb + a_colb);
            // pass lo*hi
#pragma unroll
            for (int mf = 0; mf < 4; mf++)
#pragma unroll
                for (int nf = 0; nf < 4; nf++)
                    mma16816(acc[mf][nf], af[mf], &bh[nf >> 1][(nf & 1) * 2]);
        }
        __syncthreads();
    }

    // ---- epilogue ----
    const int gid = lane >> 2;
    const int tq  = lane & 3;
#pragma unroll
    for (int mf = 0; mf < 4; mf++) {
#pragma unroll
        for (int nf = 0; nf < 4; nf++) {
            const float* a = acc[mf][nf];
            int m0 = bm + wm + mf * 16 + gid;
            int n0 = bn + wn + nf * 8 + tq * 2;
            float b0 = __ldg(&bias[n0]);
            float b1 = __ldg(&bias[n0 + 1]);
            if (mode == 0) {
                float2 v0 = make_float2(a[0] + b0, a[1] + b1);
                float2 v1 = make_float2(a[2] + b0, a[3] + b1);
                *reinterpret_cast<float2*>(&C[(size_t)m0 * 512 + n0])       = v0;
                *reinterpret_cast<float2*>(&C[(size_t)(m0 + 8) * 512 + n0]) = v1;
            } else if (mode == 1) {
                int bi0 = m0 >> 10, l0v = m0 & 1023;
                int m1 = m0 + 8;
                int bi1 = m1 >> 10, l1v = m1 & 1023;
                C[((size_t)(bi0 * 512 + n0    )) * 1024 + l0v] = a[0] + b0;
                C[((size_t)(bi0 * 512 + n0 + 1)) * 1024 + l0v] = a[1] + b1;
                C[((size_t)(bi1 * 512 + n0    )) * 1024 + l1v] = a[2] + b0;
                C[((size_t)(bi1 * 512 + n0 + 1)) * 1024 + l1v] = a[3] + b1;
            } else {
                float v0 = a[0] + b0, v1 = a[1] + b1;
                float v2 = a[2] + b0, v3 = a[3] + b1;
                __nv_bfloat162 ph0, pl0, ph1, pl1;
                ph0.x = __float2bfloat16(v0); ph0.y = __float2bfloat16(v1);
                pl0.x = __float2bfloat16(v0 - __bfloat162float(ph0.x));
                pl0.y = __float2bfloat16(v1 - __bfloat162float(ph0.y));
                ph1.x = __float2bfloat16(v2); ph1.y = __float2bfloat16(v3);
                pl1.x = __float2bfloat16(v2 - __bfloat162float(ph1.x));
                pl1.y = __float2bfloat16(v3 - __bfloat162float(ph1.y));
                *reinterpret_cast<__nv_bfloat162*>(&Chi[(size_t)m0 * 512 + n0])       = ph0;
                *reinterpret_cast<__nv_bfloat162*>(&Clo[(size_t)m0 * 512 + n0])       = pl0;
                *reinterpret_cast<__nv_bfloat162*>(&Chi[(size_t)(m0 + 8) * 512 + n0]) = ph1;
                *reinterpret_cast<__nv_bfloat162*>(&Clo[(size_t)(m0 + 8) * 512 + n0]) = pl1;
            }
        }
    }
}

// ---------------------------------------------------------------------------
// Fused attention (unchanged from passing R9 kernel)
// ---------------------------------------------------------------------------
#define SROW 1032
#define ATTN_SMEM_FLOATS (32*SROW + 64*36 + 256*68)
#define ATTN_SMEM_BYTES  (ATTN_SMEM_FLOATS * 4)

__global__ __launch_bounds__(256)
void attn_k(const float* __restrict__ Q, const float* __restrict__ Kt,
            const float* __restrict__ V, float* __restrict__ scores,
            float* __restrict__ merged)
{
    extern __shared__ float sm[];
    float* S   = sm;
    float* Qst = S + 32 * SROW;
    float* KV  = Qst + 64 * 36;

    const int tid = threadIdx.x;
    const int qt  = blockIdx.x;
    const int h   = blockIdx.y;
    const int b   = blockIdx.z;
    const int l0  = qt * 32;

    {
        const float* Qg = Q + ((size_t)(b * 1024 + l0)) * 512 + h * 64;
#pragma unroll
        for (int i = 0; i < 2; i++) {
            int idx = tid + i * 256;
            int r   = idx >> 4;
            int d4  = (idx & 15) << 2;
            float4 v = *reinterpret_cast<const float4*>(&Qg[(size_t)r * 512 + d4]);
            Qst[(d4 + 0) * 36 + r] = v.x * 0.125f;
            Qst[(d4 + 1) * 36 + r] = v.y * 0.125f;
            Qst[(d4 + 2) * 36 + r] = v.z * 0.125f;
            Qst[(d4 + 3) * 36 + r] = v.w * 0.125f;
        }
    }

    const int lane = tid & 31;
    const int w    = tid >> 5;

    {
        const int c0 = lane * 8;
        const int r0 = w * 4;
        for (int jt = 0; jt < 4; jt++) {
            __syncthreads();
            const float* Kg = Kt + ((size_t)(b * 512 + h * 64)) * 1024 + jt * 256;
#pragma unroll
            for (int i = 0; i < 16; i++) {
                int idx = tid + i * 256;
                int d   = idx >> 6;
                int c4  = (idx & 63) << 2;
                float4 v = *reinterpret_cast<const float4*>(&Kg[(size_t)d * 1024 + c4]);
                *reinterpret_cast<float4*>(&KV[d * 260 + c4]) = v;
            }
            __syncthreads();

            float acc[4][8];
#pragma unroll
            for (int i = 0; i < 4; i++)
#pragma unroll
                for (int j = 0; j < 8; j++) acc[i][j] = 0.0f;

#pragma unroll 8
            for (int d = 0; d < 64; d++) {
                float4 aq = *reinterpret_cast<const float4*>(&Qst[d * 36 + r0]);
                float4 b0 = *reinterpret_cast<const float4*>(&KV[d * 260 + c0]);
                float4 b1 = *reinterpret_cast<const float4*>(&KV[d * 260 + c0 + 4]);
                float av[4] = {aq.x, aq.y, aq.z, aq.w};
                float bv[8] = {b0.x, b0.y, b0.z, b0.w, b1.x, b1.y, b1.z, b1.w};
#pragma unroll
                for (int i = 0; i < 4; i++)
#pragma unroll
                    for (int j = 0; j < 8; j++)
                        acc[i][j] = fmaf(av[i], bv[j], acc[i][j]);
            }

#pragma unroll
            for (int i = 0; i < 4; i++) {
                float* srow = &S[(size_t)(r0 + i) * SROW + jt * 256 + c0];
                *reinterpret_cast<float4*>(srow)     = make_float4(acc[i][0], acc[i][1], acc[i][2], acc[i][3]);
                *reinterpret_cast<float4*>(srow + 4) = make_float4(acc[i][4], acc[i][5], acc[i][6], acc[i][7]);
            }
        }
        __syncthreads();
    }

    {
        for (int rr = 0; rr < 4; rr++) {
            int r = w * 4 + rr;
            float* row = &S[(size_t)r * SROW];
            float mx = -1e30f;
            for (int j = lane; j < 1024; j += 32) mx = fmaxf(mx, row[j]);
#pragma unroll
            for (int o = 16; o; o >>= 1) mx = fmaxf(mx, __shfl_xor_sync(0xffffffffu, mx, o));
            float s = 0.0f;
            for (int j = lane; j < 1024; j += 32) {
                float e = __expf(row[j] - mx);
                row[j] = e;
                s += e;
            }
#pragma unroll
            for (int o = 16; o; o >>= 1) s += __shfl_xor_sync(0xffffffffu, s, o);
            float inv = 1.0f / s;
            float* sg = scores + (((size_t)(b * 8 + h)) * 1024 + (l0 + r)) * 1024;
            for (int j = lane; j < 1024; j += 32) {
                float p = row[j] * inv;
                row[j] = p;
                sg[j]  = p;
            }
        }
    }

    {
        const int tx  = tid & 15;
        const int tyv = tid >> 4;
        const int d0  = tx * 4;
        const int r0  = tyv * 2;
        float o[2][4];
#pragma unroll
        for (int i = 0; i < 2; i++)
#pragma unroll
            for (int j = 0; j < 4; j++) o[i][j] = 0.0f;

        for (int jt = 0; jt < 4; jt++) {
            __syncthreads();
            const float* Vg = V + ((size_t)(b * 1024 + jt * 256)) * 512 + h * 64;
#pragma unroll
            for (int i = 0; i < 16; i++) {
                int idx = tid + i * 256;
                int jr  = idx >> 4;
                int d4  = (idx & 15) << 2;
                float4 v = *reinterpret_cast<const float4*>(&Vg[(size_t)jr * 512 + d4]);
                *reinterpret_cast<float4*>(&KV[jr * 68 + d4]) = v;
            }
            __syncthreads();

#pragma unroll 8
            for (int jj = 0; jj < 256; jj++) {
                float4 bv = *reinterpret_cast<const float4*>(&KV[jj * 68 + d0]);
                float a0 = S[(size_t)(r0 + 0) * SROW + jt * 256 + jj];
                float a1 = S[(size_t)(r0 + 1) * SROW + jt * 256 + jj];
                o[0][0] = fmaf(a0, bv.x, o[0][0]);
                o[0][1] = fmaf(a0, bv.y, o[0][1]);
                o[0][2] = fmaf(a0, bv.z, o[0][2]);
                o[0][3] = fmaf(a0, bv.w, o[0][3]);
                o[1][0] = fmaf(a1, bv.x, o[1][0]);
                o[1][1] = fmaf(a1, bv.y, o[1][1]);
                o[1][2] = fmaf(a1, bv.z, o[1][2]);
                o[1][3] = fmaf(a1, bv.w, o[1][3]);
            }
        }

        float* mg = merged + ((size_t)(b * 1024 + l0)) * 512 + h;
#pragma unroll
        for (int i = 0; i < 2; i++)
#pragma unroll
            for (int jd = 0; jd < 4; jd++)
                mg[(size_t)(r0 + i) * 512 + (size_t)(d0 + jd) * 8] = o[i][jd];
    }
}

// ---------------------------------------------------------------------------
// Launch
// ---------------------------------------------------------------------------
extern "C" void kernel_launch(void* const* d_in, const int* in_sizes, int n_in,
                              void* d_out, int out_size)
{
    const float* x  = (const float*)d_in[0];
    const float* Wc = (const float*)d_in[1];
    const float* bc = (const float*)d_in[2];
    const float* Wq = (const float*)d_in[3];
    const float* bq = (const float*)d_in[4];
    const float* Wk = (const float*)d_in[5];
    const float* bk = (const float*)d_in[6];
    const float* Wv = (const float*)d_in[7];
    const float* bv = (const float*)d_in[8];
    const float* Wo = (const float*)d_in[9];
    const float* bo = (const float*)d_in[10];

    float* out    = (float*)d_out;
    float* scores = out + (size_t)Bb * Ll * Dd;

    float *Qb, *Ktb, *Vb, *mg;
    cudaGetSymbolAddress((void**)&Qb,  g_Q);
    cudaGetSymbolAddress((void**)&Ktb, g_Kt);
    cudaGetSymbolAddress((void**)&Vb,  g_V);
    cudaGetSymbolAddress((void**)&mg,  g_mg);

    __nv_bfloat16 *xhi, *xlo, *xrhi, *xrlo, *mghi, *mglo, *whi, *wlo;
    cudaGetSymbolAddress((void**)&xhi,  g_xhi);
    cudaGetSymbolAddress((void**)&xlo,  g_xlo);
    cudaGetSymbolAddress((void**)&xrhi, g_xrhi);
    cudaGetSymbolAddress((void**)&xrlo, g_xrlo);
    cudaGetSymbolAddress((void**)&mghi, g_mghi);
    cudaGetSymbolAddress((void**)&mglo, g_mglo);
    cudaGetSymbolAddress((void**)&whi,  g_whi);
    cudaGetSymbolAddress((void**)&wlo,  g_wlo);

    cudaFuncSetAttribute((const void*)attn_k,
                         cudaFuncAttributeMaxDynamicSharedMemorySize, ATTN_SMEM_BYTES);

    const int WN = Dd * Dd;           // 262144 elems per weight
    cvt_split<<<(Mrows*Dd/4 + 255)/256, 256>>>(x,  xhi, xlo, Mrows*Dd/4);
    cvt_split<<<(WN/4 + 255)/256, 256>>>(Wc, whi + 0*WN, wlo + 0*WN, WN/4);
    cvt_split<<<(WN/4 + 255)/256, 256>>>(Wq, whi + 1*WN, wlo + 1*WN, WN/4);
    cvt_split<<<(WN/4 + 255)/256, 256>>>(Wk, whi + 2*WN, wlo + 2*WN, WN/4);
    cvt_split<<<(WN/4 + 255)/256, 256>>>(Wv, whi + 3*WN, wlo + 3*WN, WN/4);
    cvt_split<<<(WN/4 + 255)/256, 256>>>(Wo, whi + 4*WN, wlo + 4*WN, WN/4);

    dim3 gg(Mrows / 128, Dd / 128);   // (64, 4)

    // x_r = x @ Wc^T + bc  (split bf16 output)
    tg_gemm<<<gg, 256>>>(xhi, xlo, whi + 0*WN, wlo + 0*WN, bc,
                         nullptr, xrhi, xrlo, 2);
    // Q = x @ Wq^T + bq
    tg_gemm<<<gg, 256>>>(xhi, xlo, whi + 1*WN, wlo + 1*WN, bq,
                         Qb, nullptr, nullptr, 0);
    // K = x_r @ Wk^T + bk  (transposed Kt output)
    tg_gemm<<<gg, 256>>>(xrhi, xrlo, whi + 2*WN, wlo + 2*WN, bk,
                         Ktb, nullptr, nullptr, 1);
    // V = x_r @ Wv^T + bv
    tg_gemm<<<gg, 256>>>(xrhi, xrlo, whi + 3*WN, wlo + 3*WN, bv,
                         Vb, nullptr, nullptr, 0);

    attn_k<<<dim3(32, Hh, Bb), 256, ATTN_SMEM_BYTES>>>(Qb, Ktb, Vb, scores, mg);

    cvt_split<<<(Mrows*Dd/4 + 255)/256, 256>>>(mg, mghi, mglo, Mrows*Dd/4);
    // out = merged @ Wo^T + bo
    tg_gemm<<<gg, 256>>>(mghi, mglo, whi + 4*WN, wlo + 4*WN, bo,
                         out, nullptr, nullptr, 0);
}